// round 1
// baseline (speedup 1.0000x reference)
#include <cuda_runtime.h>
#include <cuda_bf16.h>

// Problem dims (fixed by the reference)
static constexpr int N_IN  = 2048;
static constexpr int N_HID = 4096;
static constexpr int N_OUT = 1024;
static constexpr int N_TOT = 7168;   // 2048 + 4096 + 1024
static constexpr int BATCH = 4096;

#define BM 128
#define BN 128
#define BK 16

// Scratch for the hidden activation (allocation-free rule: __device__ global).
__device__ float g_hidden[(size_t)BATCH * N_HID];

// C[M,N] = Aseg @ B, where the A operand is split along K into two row-major
// segments: A0 (K0 columns, leading dim lda0) followed by A1 (K-K0 columns,
// leading dim lda1). Each BK=16 k-tile lies entirely within one segment
// (K0 is a multiple of BK). Optional ReLU epilogue.
__global__ __launch_bounds__(256, 2)
void sgemm_split_kernel(const float* __restrict__ A0, int lda0, int K0,
                        const float* __restrict__ A1, int lda1,
                        const float* __restrict__ B, int ldb,
                        float* __restrict__ C, int ldc,
                        int K, int do_relu)
{
    __shared__ float As[BK][BM];   // transposed A tile: As[k][m]
    __shared__ float Bs[BK][BN];   // Bs[k][n]

    const int tid  = threadIdx.x;
    const int brow = blockIdx.y * BM;
    const int bcol = blockIdx.x * BN;

    // Warp tiling: 8 warps in a 4(row) x 2(col) grid, each warp covers 32x64.
    // Lanes in a warp: 4(row) x 8(col), each thread 8x8.
    const int warp_id  = tid >> 5;
    const int lane     = tid & 31;
    const int warp_row = warp_id & 3;        // 0..3
    const int warp_col = warp_id >> 2;       // 0..1
    const int lane_row = lane >> 3;          // 0..3
    const int lane_col = lane & 7;           // 0..7
    const int crow = warp_row * 32 + lane_row * 8;   // 0..120
    const int ccol = warp_col * 64 + lane_col * 8;   // 0..120

    float acc[8][8];
    #pragma unroll
    for (int i = 0; i < 8; i++)
        #pragma unroll
        for (int j = 0; j < 8; j++)
            acc[i][j] = 0.0f;

    for (int k0 = 0; k0 < K; k0 += BK) {
        // ---- Load A tile (128 rows x 16 k) = 512 float4, 2 per thread ----
        #pragma unroll
        for (int i = 0; i < 2; i++) {
            int v   = tid + i * 256;        // 0..511
            int ar  = v >> 2;               // row within tile 0..127
            int akv = (v & 3) * 4;          // k offset 0,4,8,12
            int kg  = k0 + akv;             // global k of this float4
            const float* Ap; long lda; int kl;
            if (kg < K0) { Ap = A0; lda = lda0; kl = kg; }
            else         { Ap = A1; lda = lda1; kl = kg - K0; }
            float4 f = *(const float4*)(Ap + (long)(brow + ar) * lda + kl);
            As[akv + 0][ar] = f.x;
            As[akv + 1][ar] = f.y;
            As[akv + 2][ar] = f.z;
            As[akv + 3][ar] = f.w;
        }
        // ---- Load B tile (16 k x 128 n) = 512 float4, 2 per thread ----
        #pragma unroll
        for (int i = 0; i < 2; i++) {
            int v  = tid + i * 256;         // 0..511
            int bk = v >> 5;                // 0..15
            int bn = (v & 31) * 4;          // 0..124
            float4 f = *(const float4*)(B + (long)(k0 + bk) * ldb + bcol + bn);
            *(float4*)&Bs[bk][bn] = f;
        }
        __syncthreads();

        // ---- Compute 8x8 per thread over BK=16 ----
        #pragma unroll
        for (int kk = 0; kk < BK; kk++) {
            float a[8], b[8];
            *(float4*)&a[0] = *(const float4*)&As[kk][crow];
            *(float4*)&a[4] = *(const float4*)&As[kk][crow + 4];
            *(float4*)&b[0] = *(const float4*)&Bs[kk][ccol];
            *(float4*)&b[4] = *(const float4*)&Bs[kk][ccol + 4];
            #pragma unroll
            for (int i = 0; i < 8; i++)
                #pragma unroll
                for (int j = 0; j < 8; j++)
                    acc[i][j] = fmaf(a[i], b[j], acc[i][j]);
        }
        __syncthreads();
    }

    // ---- Epilogue: optional ReLU, vectorized store ----
    #pragma unroll
    for (int i = 0; i < 8; i++) {
        if (do_relu) {
            #pragma unroll
            for (int j = 0; j < 8; j++)
                acc[i][j] = fmaxf(acc[i][j], 0.0f);
        }
        float* Crow = C + (long)(brow + crow + i) * ldc + bcol + ccol;
        *(float4*)(Crow + 0) = make_float4(acc[i][0], acc[i][1], acc[i][2], acc[i][3]);
        *(float4*)(Crow + 4) = make_float4(acc[i][4], acc[i][5], acc[i][6], acc[i][7]);
    }
}

extern "C" void kernel_launch(void* const* d_in, const int* in_sizes, int n_in,
                              void* d_out, int out_size)
{
    const float* x       = (const float*)d_in[0];   // (4096, 2048)
    const float* weights = (const float*)d_in[1];   // (7168, 7168)
    // d_in[2] = structure_mask: every entry the forward pass reads is 1 -> unused.
    float* out = (float*)d_out;                     // (4096, 1024)

    void* hidden_ptr = nullptr;
    cudaGetSymbolAddress(&hidden_ptr, g_hidden);
    float* hidden = (float*)hidden_ptr;

    // GEMM1: hidden = relu(x @ W[0:2048, 2048:6144])
    {
        dim3 grid(N_HID / BN, BATCH / BM);   // (32, 32)
        sgemm_split_kernel<<<grid, 256>>>(
            x, N_IN, N_IN,                // A0 = x, K0 = 2048 (entire K)
            nullptr, 0,                   // no second segment
            weights + N_IN, N_TOT,        // B = W cols [2048, 6144), ldb = 7168
            hidden, N_HID,
            N_IN, /*relu=*/1);
    }

    // GEMM2: out = [x | hidden] @ W[0:6144, 6144:7168]
    {
        dim3 grid(N_OUT / BN, BATCH / BM);   // (8, 32)
        sgemm_split_kernel<<<grid, 256>>>(
            x, N_IN, N_IN,                // first K segment: x (K0 = 2048)
            hidden, N_HID,                // second segment: hidden (K = 2048..6144)
            weights + N_IN + N_HID, N_TOT,// B = W cols [6144, 7168), ldb = 7168
            out, N_OUT,
            N_IN + N_HID, /*relu=*/0);
    }
}

// round 3
// speedup vs baseline: 3.3246x; 3.3246x over previous
#include <cuda_runtime.h>
#include <cuda_bf16.h>
#include <cstdint>
#include <cstddef>

// ---------------------------------------------------------------------------
// Problem dims
// ---------------------------------------------------------------------------
static constexpr int N_IN  = 2048;
static constexpr int N_HID = 4096;
static constexpr int N_OUT = 1024;
static constexpr int N_TOT = 7168;
static constexpr int BATCH = 4096;
static constexpr int KA    = N_IN + N_HID;   // 6144 : packed A = [x | hidden]

// ---------------------------------------------------------------------------
// Device scratch (allocation-free rule: __device__ globals)
// ---------------------------------------------------------------------------
__device__ __align__(1024) __nv_bfloat16 g_Ah[(size_t)BATCH * KA];
__device__ __align__(1024) __nv_bfloat16 g_Al[(size_t)BATCH * KA];
__device__ __align__(1024) __nv_bfloat16 g_B1h[(size_t)N_HID * N_IN];
__device__ __align__(1024) __nv_bfloat16 g_B1l[(size_t)N_HID * N_IN];
__device__ __align__(1024) __nv_bfloat16 g_B2h[(size_t)N_OUT * KA];
__device__ __align__(1024) __nv_bfloat16 g_B2l[(size_t)N_OUT * KA];

#define DEVFN __device__ __forceinline__

DEVFN uint32_t smem_u32(const void* p) {
    uint32_t a;
    asm("{ .reg .u64 t; cvta.to.shared.u64 t, %1; cvt.u32.u64 %0, t; }"
        : "=r"(a) : "l"(p));
    return a;
}

DEVFN void cp16(uint32_t s, const void* g) {
    asm volatile("cp.async.cg.shared.global [%0], [%1], 16;"
                 :: "r"(s), "l"(g));
}
DEVFN void cp_commit() { asm volatile("cp.async.commit_group;"); }
template <int N> DEVFN void cp_wait() {
    asm volatile("cp.async.wait_group %0;" :: "n"(N));
}

DEVFN void ldsm4(uint32_t* r, uint32_t a) {
    asm volatile("ldmatrix.sync.aligned.m8n8.x4.shared.b16 {%0,%1,%2,%3}, [%4];"
                 : "=r"(r[0]), "=r"(r[1]), "=r"(r[2]), "=r"(r[3]) : "r"(a));
}

DEVFN void mma16816(float* d, const uint32_t* a, uint32_t b0, uint32_t b1) {
    asm volatile(
        "mma.sync.aligned.m16n8k16.row.col.f32.bf16.bf16.f32 "
        "{%0,%1,%2,%3}, {%4,%5,%6,%7}, {%8,%9}, {%0,%1,%2,%3};"
        : "+f"(d[0]), "+f"(d[1]), "+f"(d[2]), "+f"(d[3])
        : "r"(a[0]), "r"(a[1]), "r"(a[2]), "r"(a[3]), "r"(b0), "r"(b1));
}

DEVFN uint32_t pack2u(__nv_bfloat16 a, __nv_bfloat16 b) {
    return (uint32_t)__bfloat16_as_ushort(a) |
           ((uint32_t)__bfloat16_as_ushort(b) << 16);
}

// ---------------------------------------------------------------------------
// Packing kernels
// ---------------------------------------------------------------------------
__global__ void pack_x_kernel(const float4* __restrict__ x) {
    int idx = blockIdx.x * blockDim.x + threadIdx.x;   // over BATCH*N_IN/4
    int m  = idx / (N_IN / 4);
    int k4 = idx % (N_IN / 4);
    float4 v = x[idx];
    float vv[4] = {v.x, v.y, v.z, v.w};
    __nv_bfloat16 h[4], l[4];
    #pragma unroll
    for (int i = 0; i < 4; i++) {
        h[i] = __float2bfloat16(vv[i]);
        l[i] = __float2bfloat16(vv[i] - __bfloat162float(h[i]));
    }
    size_t o = (size_t)m * KA + k4 * 4;
    uint2 uh; uh.x = pack2u(h[0], h[1]); uh.y = pack2u(h[2], h[3]);
    uint2 ul; ul.x = pack2u(l[0], l[1]); ul.y = pack2u(l[2], l[3]);
    *(uint2*)(g_Ah + o) = uh;
    *(uint2*)(g_Al + o) = ul;
}

// out[n][k] = split(W[k][col0 + n]) — tiled transpose
__global__ void pack_w_kernel(const float* __restrict__ W, int col0,
                              __nv_bfloat16* __restrict__ outH,
                              __nv_bfloat16* __restrict__ outL, int pitchK) {
    __shared__ float t[32][33];
    int nb = blockIdx.x * 32, kb = blockIdx.y * 32;
    int tx = threadIdx.x, ty = threadIdx.y;   // (32, 8)
    #pragma unroll
    for (int i = 0; i < 4; i++) {
        int k = kb + ty + i * 8;
        t[ty + i * 8][tx] = W[(size_t)k * N_TOT + col0 + nb + tx];
    }
    __syncthreads();
    #pragma unroll
    for (int i = 0; i < 4; i++) {
        int n = nb + ty + i * 8;
        int k = kb + tx;
        float v = t[tx][ty + i * 8];
        __nv_bfloat16 h = __float2bfloat16(v);
        __nv_bfloat16 l = __float2bfloat16(v - __bfloat162float(h));
        outH[(size_t)n * pitchK + k] = h;
        outL[(size_t)n * pitchK + k] = l;
    }
}

// ---------------------------------------------------------------------------
// Split-precision bf16 GEMM on mma.sync (HMMA), cp.async pipeline.
// C[128,128] per CTA; K consumed in chunks of 64; 3 products share accums.
// ---------------------------------------------------------------------------
static constexpr int BM = 128, BN = 128, BK = 64;
static constexpr int STAGES  = 3;
static constexpr int TILE_B  = BM * BK * 2;        // 16 KB
static constexpr int STAGE_B = 4 * TILE_B;         // Ah, Al, Bh, Bl = 64 KB
static constexpr int SMEM_GEMM = STAGES * STAGE_B + 128;

template <bool RELU_PACK>
__global__ __launch_bounds__(256, 1)
void gemm_hl(const __nv_bfloat16* __restrict__ Ah,
             const __nv_bfloat16* __restrict__ Al, int ldA,
             const __nv_bfloat16* __restrict__ Bh,
             const __nv_bfloat16* __restrict__ Bl, int ldB,
             int kChunks,
             __nv_bfloat16* __restrict__ outH,
             __nv_bfloat16* __restrict__ outL, int outColOff,
             float* __restrict__ outF, int ldOut)
{
    extern __shared__ char smraw[];
    uint32_t sb = (smem_u32(smraw) + 127u) & ~127u;

    const int tid  = threadIdx.x;
    const int wid  = tid >> 5;
    const int lane = tid & 31;
    const int m0 = blockIdx.y * BM, n0 = blockIdx.x * BN;

    // ---- loader precompute: each thread moves 4x16B per tile per stage ----
    const int c16 = tid & 7;          // 16B unit within 128B row
    const int rb  = tid >> 3;         // base row (0..31)
    const uint32_t lxor = (uint32_t)(rb & 7) << 4;
    uint32_t soff[4];
    #pragma unroll
    for (int j = 0; j < 4; j++)
        soff[j] = (uint32_t)(rb + 32 * j) * 128 + (((uint32_t)c16 * 16) ^ lxor);

    const __nv_bfloat16* gAh = Ah + (size_t)(m0 + rb) * ldA + c16 * 8;
    const __nv_bfloat16* gAl = Al + (size_t)(m0 + rb) * ldA + c16 * 8;
    const __nv_bfloat16* gBh = Bh + (size_t)(n0 + rb) * ldB + c16 * 8;
    const __nv_bfloat16* gBl = Bl + (size_t)(n0 + rb) * ldB + c16 * 8;

    auto load_stage = [&](int slot, int chunk) {
        uint32_t st = sb + slot * STAGE_B;
        int kcol = chunk * BK;
        #pragma unroll
        for (int j = 0; j < 4; j++) {
            size_t ar = (size_t)(32 * j) * ldA;
            size_t br = (size_t)(32 * j) * ldB;
            cp16(st + soff[j],              gAh + ar + kcol);
            cp16(st + TILE_B + soff[j],     gAl + ar + kcol);
            cp16(st + 2 * TILE_B + soff[j], gBh + br + kcol);
            cp16(st + 3 * TILE_B + soff[j], gBl + br + kcol);
        }
    };

    // ---- fragment address precompute (manual SW128 swizzle) ----
    const int warp_m = wid >> 2;      // 0..1, 64 rows each
    const int warp_n = wid & 3;       // 0..3, 32 cols each
    const uint32_t aOff0 = (uint32_t)(warp_m * 64 + (lane & 15)) * 128;
    const uint32_t aKq   = ((uint32_t)lane >> 4) * 16;
    const uint32_t amask = ((uint32_t)lane & 7) << 4;
    const uint32_t bOff0 =
        (uint32_t)(warp_n * 32 + (lane & 7) + ((lane >> 4) << 3)) * 128;
    const uint32_t bKq   = (((uint32_t)lane >> 3) & 1) * 16;
    const uint32_t bmask = ((uint32_t)lane & 7) << 4;

    float acc[4][4][4];
    #pragma unroll
    for (int mt = 0; mt < 4; mt++)
        #pragma unroll
        for (int nt = 0; nt < 4; nt++)
            #pragma unroll
            for (int r = 0; r < 4; r++)
                acc[mt][nt][r] = 0.0f;

    // ---- pipeline ----
    int pro = kChunks < STAGES ? kChunks : STAGES;
    for (int i = 0; i < pro; i++) { load_stage(i, i); cp_commit(); }
    int issued = pro;

    int s = 0;
    for (int c = 0; c < kChunks; c++) {
        cp_wait<STAGES - 1>();
        __syncthreads();
        uint32_t st = sb + s * STAGE_B;

        #pragma unroll
        for (int ks = 0; ks < 4; ks++) {
            const uint32_t kb = ks * 32;
            uint32_t ah[4][4], al[4][4], bh[2][4], bl[2][4];
            #pragma unroll
            for (int mt = 0; mt < 4; mt++)
                ldsm4(ah[mt], st + aOff0 + mt * 2048 + ((kb + aKq) ^ amask));
            #pragma unroll
            for (int mt = 0; mt < 4; mt++)
                ldsm4(al[mt], st + TILE_B + aOff0 + mt * 2048 + ((kb + aKq) ^ amask));
            #pragma unroll
            for (int ng = 0; ng < 2; ng++)
                ldsm4(bh[ng], st + 2 * TILE_B + bOff0 + ng * 2048 + ((kb + bKq) ^ bmask));
            #pragma unroll
            for (int ng = 0; ng < 2; ng++)
                ldsm4(bl[ng], st + 3 * TILE_B + bOff0 + ng * 2048 + ((kb + bKq) ^ bmask));

            #pragma unroll
            for (int mt = 0; mt < 4; mt++)
                #pragma unroll
                for (int nt = 0; nt < 4; nt++) {
                    const int ng = nt >> 1, hf = nt & 1;
                    mma16816(acc[mt][nt], ah[mt], bh[ng][hf * 2], bh[ng][hf * 2 + 1]);
                    mma16816(acc[mt][nt], ah[mt], bl[ng][hf * 2], bl[ng][hf * 2 + 1]);
                    mma16816(acc[mt][nt], al[mt], bh[ng][hf * 2], bh[ng][hf * 2 + 1]);
                }
        }

        __syncthreads();
        if (issued < kChunks) { load_stage(s, issued); issued++; }
        cp_commit();
        if (++s == STAGES) s = 0;
    }

    // ---- epilogue ----
    const int gr  = lane >> 2;        // 0..7
    const int gc2 = (lane & 3) * 2;   // 0,2,4,6
    #pragma unroll
    for (int mt = 0; mt < 4; mt++)
        #pragma unroll
        for (int nt = 0; nt < 4; nt++)
            #pragma unroll
            for (int hf = 0; hf < 2; hf++) {   // hf=0: c0,c1 ; hf=1: c2,c3
                int row = m0 + warp_m * 64 + mt * 16 + gr + hf * 8;
                int col = n0 + warp_n * 32 + nt * 8 + gc2;
                float v0 = acc[mt][nt][hf * 2];
                float v1 = acc[mt][nt][hf * 2 + 1];
                if (RELU_PACK) {
                    v0 = fmaxf(v0, 0.0f);
                    v1 = fmaxf(v1, 0.0f);
                    __nv_bfloat16 h0 = __float2bfloat16(v0);
                    __nv_bfloat16 h1 = __float2bfloat16(v1);
                    __nv_bfloat16 l0 = __float2bfloat16(v0 - __bfloat162float(h0));
                    __nv_bfloat16 l1 = __float2bfloat16(v1 - __bfloat162float(h1));
                    size_t o = (size_t)row * KA + outColOff + col;
                    *(uint32_t*)(outH + o) = pack2u(h0, h1);
                    *(uint32_t*)(outL + o) = pack2u(l0, l1);
                } else {
                    float2 f2 = make_float2(v0, v1);
                    *(float2*)(outF + (size_t)row * ldOut + col) = f2;
                }
            }
}

// ---------------------------------------------------------------------------
// Host side
// ---------------------------------------------------------------------------
extern "C" void kernel_launch(void* const* d_in, const int* in_sizes, int n_in,
                              void* d_out, int out_size)
{
    const float* x = (const float*)d_in[0];        // (4096, 2048)
    const float* W = (const float*)d_in[1];        // (7168, 7168)
    float* out = (float*)d_out;                    // (4096, 1024)

    void *pAh, *pAl, *pB1h, *pB1l, *pB2h, *pB2l;
    cudaGetSymbolAddress(&pAh,  g_Ah);
    cudaGetSymbolAddress(&pAl,  g_Al);
    cudaGetSymbolAddress(&pB1h, g_B1h);
    cudaGetSymbolAddress(&pB1l, g_B1l);
    cudaGetSymbolAddress(&pB2h, g_B2h);
    cudaGetSymbolAddress(&pB2l, g_B2l);

    cudaFuncSetAttribute(gemm_hl<true>,
        cudaFuncAttributeMaxDynamicSharedMemorySize, SMEM_GEMM);
    cudaFuncSetAttribute(gemm_hl<false>,
        cudaFuncAttributeMaxDynamicSharedMemorySize, SMEM_GEMM);

    // 1) pack x into Ah/Al cols [0, 2048)
    pack_x_kernel<<<(BATCH * N_IN / 4) / 256, 256>>>((const float4*)x);

    // 2) transpose + split W slices
    pack_w_kernel<<<dim3(N_HID / 32, N_IN / 32), dim3(32, 8)>>>(
        W, N_IN, (__nv_bfloat16*)pB1h, (__nv_bfloat16*)pB1l, N_IN);
    pack_w_kernel<<<dim3(N_OUT / 32, KA / 32), dim3(32, 8)>>>(
        W, N_IN + N_HID, (__nv_bfloat16*)pB2h, (__nv_bfloat16*)pB2l, KA);

    // 3) GEMM1: hidden = relu(x @ W1); epilogue packs hi/lo into A cols [2048,6144)
    gemm_hl<true><<<dim3(N_HID / BN, BATCH / BM), 256, SMEM_GEMM>>>(
        (const __nv_bfloat16*)pAh, (const __nv_bfloat16*)pAl, KA,
        (const __nv_bfloat16*)pB1h, (const __nv_bfloat16*)pB1l, N_IN,
        N_IN / BK,
        (__nv_bfloat16*)pAh, (__nv_bfloat16*)pAl, N_IN, nullptr, 0);

    // 4) GEMM2: out = [x | hidden] @ W2
    gemm_hl<false><<<dim3(N_OUT / BN, BATCH / BM), 256, SMEM_GEMM>>>(
        (const __nv_bfloat16*)pAh, (const __nv_bfloat16*)pAl, KA,
        (const __nv_bfloat16*)pB2h, (const __nv_bfloat16*)pB2l, KA,
        KA / BK,
        nullptr, nullptr, 0, out, N_OUT);
}

// round 4
// speedup vs baseline: 8.7720x; 2.6385x over previous
#include <cuda_runtime.h>
#include <cuda_fp16.h>
#include <cstdint>
#include <cstddef>

// ---------------------------------------------------------------------------
// Problem dims
// ---------------------------------------------------------------------------
static constexpr int N_IN  = 2048;
static constexpr int N_HID = 4096;
static constexpr int N_OUT = 1024;
static constexpr int N_TOT = 7168;
static constexpr int BATCH = 4096;
static constexpr int KA    = N_IN + N_HID;   // 6144 : packed A = [x | hidden]

// ---------------------------------------------------------------------------
// Device scratch (allocation-free rule: __device__ globals)
// ---------------------------------------------------------------------------
__device__ __align__(1024) __half g_A[(size_t)BATCH * KA];       // [x | hidden] fp16
__device__ __align__(1024) __half g_B1[(size_t)N_HID * N_IN];    // W1^T fp16
__device__ __align__(1024) __half g_B2[(size_t)N_OUT * KA];      // W2^T fp16

#define DEVFN __device__ __forceinline__

DEVFN uint32_t smem_u32(const void* p) {
    uint32_t a;
    asm("{ .reg .u64 t; cvta.to.shared.u64 t, %1; cvt.u32.u64 %0, t; }"
        : "=r"(a) : "l"(p));
    return a;
}

DEVFN void cp16(uint32_t s, const void* g) {
    asm volatile("cp.async.cg.shared.global [%0], [%1], 16;"
                 :: "r"(s), "l"(g));
}
DEVFN void cp_commit() { asm volatile("cp.async.commit_group;"); }
template <int N> DEVFN void cp_wait() {
    asm volatile("cp.async.wait_group %0;" :: "n"(N));
}

DEVFN void ldsm4(uint32_t* r, uint32_t a) {
    asm volatile("ldmatrix.sync.aligned.m8n8.x4.shared.b16 {%0,%1,%2,%3}, [%4];"
                 : "=r"(r[0]), "=r"(r[1]), "=r"(r[2]), "=r"(r[3]) : "r"(a));
}

DEVFN void mma16816(float* d, const uint32_t* a, uint32_t b0, uint32_t b1) {
    asm volatile(
        "mma.sync.aligned.m16n8k16.row.col.f32.f16.f16.f32 "
        "{%0,%1,%2,%3}, {%4,%5,%6,%7}, {%8,%9}, {%0,%1,%2,%3};"
        : "+f"(d[0]), "+f"(d[1]), "+f"(d[2]), "+f"(d[3])
        : "r"(a[0]), "r"(a[1]), "r"(a[2]), "r"(a[3]), "r"(b0), "r"(b1));
}

DEVFN uint32_t pack2h(__half a, __half b) {
    return (uint32_t)__half_as_ushort(a) |
           ((uint32_t)__half_as_ushort(b) << 16);
}

// ---------------------------------------------------------------------------
// Packing kernels
// ---------------------------------------------------------------------------
__global__ void pack_x_kernel(const float4* __restrict__ x) {
    int idx = blockIdx.x * blockDim.x + threadIdx.x;   // over BATCH*N_IN/4
    int m  = idx / (N_IN / 4);
    int k4 = idx % (N_IN / 4);
    float4 v = x[idx];
    uint2 u;
    u.x = pack2h(__float2half(v.x), __float2half(v.y));
    u.y = pack2h(__float2half(v.z), __float2half(v.w));
    *(uint2*)(g_A + (size_t)m * KA + k4 * 4) = u;
}

// out[n][k] = fp16(W[k][col0 + n]) — tiled transpose
__global__ void pack_w_kernel(const float* __restrict__ W, int col0,
                              __half* __restrict__ outB, int pitchK) {
    __shared__ float t[32][33];
    int nb = blockIdx.x * 32, kb = blockIdx.y * 32;
    int tx = threadIdx.x, ty = threadIdx.y;   // (32, 8)
    #pragma unroll
    for (int i = 0; i < 4; i++) {
        int k = kb + ty + i * 8;
        t[ty + i * 8][tx] = W[(size_t)k * N_TOT + col0 + nb + tx];
    }
    __syncthreads();
    #pragma unroll
    for (int i = 0; i < 4; i++) {
        int n = nb + ty + i * 8;
        int k = kb + tx;
        outB[(size_t)n * pitchK + k] = __float2half(t[tx][ty + i * 8]);
    }
}

// ---------------------------------------------------------------------------
// fp16 GEMM on mma.sync (HMMA), cp.async 3-stage pipeline, fp32 accumulate.
// C[128,128] per CTA; K consumed in chunks of 64.
// ---------------------------------------------------------------------------
static constexpr int BM = 128, BN = 128, BK = 64;
static constexpr int STAGES  = 3;
static constexpr int TILE_B  = BM * BK * 2;        // 16 KB
static constexpr int STAGE_B = 2 * TILE_B;         // A + B = 32 KB
static constexpr int SMEM_GEMM = STAGES * STAGE_B + 128;   // ~96 KB

template <bool RELU_PACK>
__global__ __launch_bounds__(256, 2)
void gemm_f16(const __half* __restrict__ A, int ldA,
              const __half* __restrict__ B, int ldB,
              int kChunks,
              __half* __restrict__ outHalf, int outColOff,
              float* __restrict__ outF, int ldOut)
{
    extern __shared__ char smraw[];
    uint32_t sb = (smem_u32(smraw) + 127u) & ~127u;

    const int tid  = threadIdx.x;
    const int wid  = tid >> 5;
    const int lane = tid & 31;
    const int m0 = blockIdx.y * BM, n0 = blockIdx.x * BN;

    // ---- loader precompute: each thread moves 4x16B per tile per stage ----
    const int c16 = tid & 7;          // 16B unit within 128B row
    const int rb  = tid >> 3;         // base row (0..31)
    const uint32_t lxor = (uint32_t)(rb & 7) << 4;
    uint32_t soff[4];
    #pragma unroll
    for (int j = 0; j < 4; j++)
        soff[j] = (uint32_t)(rb + 32 * j) * 128 + (((uint32_t)c16 * 16) ^ lxor);

    const __half* gA = A + (size_t)(m0 + rb) * ldA + c16 * 8;
    const __half* gB = B + (size_t)(n0 + rb) * ldB + c16 * 8;

    auto load_stage = [&](int slot, int chunk) {
        uint32_t st = sb + slot * STAGE_B;
        int kcol = chunk * BK;
        #pragma unroll
        for (int j = 0; j < 4; j++) {
            cp16(st + soff[j],          gA + (size_t)(32 * j) * ldA + kcol);
            cp16(st + TILE_B + soff[j], gB + (size_t)(32 * j) * ldB + kcol);
        }
    };

    // ---- fragment address precompute (manual SW128 swizzle) ----
    const int warp_m = wid >> 2;      // 0..1, 64 rows each
    const int warp_n = wid & 3;       // 0..3, 32 cols each
    const uint32_t aOff0 = (uint32_t)(warp_m * 64 + (lane & 15)) * 128;
    const uint32_t aKq   = ((uint32_t)lane >> 4) * 16;
    const uint32_t amask = ((uint32_t)lane & 7) << 4;
    const uint32_t bOff0 =
        (uint32_t)(warp_n * 32 + (lane & 7) + ((lane >> 4) << 3)) * 128;
    const uint32_t bKq   = (((uint32_t)lane >> 3) & 1) * 16;
    const uint32_t bmask = ((uint32_t)lane & 7) << 4;

    float acc[4][4][4];
    #pragma unroll
    for (int mt = 0; mt < 4; mt++)
        #pragma unroll
        for (int nt = 0; nt < 4; nt++)
            #pragma unroll
            for (int r = 0; r < 4; r++)
                acc[mt][nt][r] = 0.0f;

    // ---- pipeline ----
    int pro = kChunks < STAGES ? kChunks : STAGES;
    for (int i = 0; i < pro; i++) { load_stage(i, i); cp_commit(); }
    int issued = pro;

    int s = 0;
    for (int c = 0; c < kChunks; c++) {
        cp_wait<STAGES - 1>();
        __syncthreads();
        uint32_t st = sb + s * STAGE_B;

        #pragma unroll
        for (int ks = 0; ks < 4; ks++) {
            const uint32_t kb = ks * 32;
            uint32_t ah[4][4], bf[2][4];
            #pragma unroll
            for (int mt = 0; mt < 4; mt++)
                ldsm4(ah[mt], st + aOff0 + mt * 2048 + ((kb + aKq) ^ amask));
            #pragma unroll
            for (int ng = 0; ng < 2; ng++)
                ldsm4(bf[ng], st + TILE_B + bOff0 + ng * 2048 + ((kb + bKq) ^ bmask));

            #pragma unroll
            for (int mt = 0; mt < 4; mt++)
                #pragma unroll
                for (int nt = 0; nt < 4; nt++) {
                    const int ng = nt >> 1, hf = nt & 1;
                    mma16816(acc[mt][nt], ah[mt], bf[ng][hf * 2], bf[ng][hf * 2 + 1]);
                }
        }

        __syncthreads();
        if (issued < kChunks) { load_stage(s, issued); issued++; }
        cp_commit();
        if (++s == STAGES) s = 0;
    }

    // ---- epilogue ----
    const int gr  = lane >> 2;        // 0..7
    const int gc2 = (lane & 3) * 2;   // 0,2,4,6
    #pragma unroll
    for (int mt = 0; mt < 4; mt++)
        #pragma unroll
        for (int nt = 0; nt < 4; nt++)
            #pragma unroll
            for (int hf = 0; hf < 2; hf++) {   // hf=0: c0,c1 ; hf=1: c2,c3
                int row = m0 + warp_m * 64 + mt * 16 + gr + hf * 8;
                int col = n0 + warp_n * 32 + nt * 8 + gc2;
                float v0 = acc[mt][nt][hf * 2];
                float v1 = acc[mt][nt][hf * 2 + 1];
                if (RELU_PACK) {
                    v0 = fmaxf(v0, 0.0f);
                    v1 = fmaxf(v1, 0.0f);
                    size_t o = (size_t)row * KA + outColOff + col;
                    *(uint32_t*)(outHalf + o) =
                        pack2h(__float2half(v0), __float2half(v1));
                } else {
                    *(float2*)(outF + (size_t)row * ldOut + col) =
                        make_float2(v0, v1);
                }
            }
}

// ---------------------------------------------------------------------------
// Host side
// ---------------------------------------------------------------------------
extern "C" void kernel_launch(void* const* d_in, const int* in_sizes, int n_in,
                              void* d_out, int out_size)
{
    const float* x = (const float*)d_in[0];        // (4096, 2048)
    const float* W = (const float*)d_in[1];        // (7168, 7168)
    float* out = (float*)d_out;                    // (4096, 1024)

    void *pA, *pB1, *pB2;
    cudaGetSymbolAddress(&pA,  g_A);
    cudaGetSymbolAddress(&pB1, g_B1);
    cudaGetSymbolAddress(&pB2, g_B2);

    cudaFuncSetAttribute(gemm_f16<true>,
        cudaFuncAttributeMaxDynamicSharedMemorySize, SMEM_GEMM);
    cudaFuncSetAttribute(gemm_f16<false>,
        cudaFuncAttributeMaxDynamicSharedMemorySize, SMEM_GEMM);

    // 1) pack x into A cols [0, 2048)
    pack_x_kernel<<<(BATCH * N_IN / 4) / 256, 256>>>((const float4*)x);

    // 2) transpose W slices to fp16 K-major
    pack_w_kernel<<<dim3(N_HID / 32, N_IN / 32), dim3(32, 8)>>>(
        W, N_IN, (__half*)pB1, N_IN);
    pack_w_kernel<<<dim3(N_OUT / 32, KA / 32), dim3(32, 8)>>>(
        W, N_IN + N_HID, (__half*)pB2, KA);

    // 3) GEMM1: hidden = relu(x @ W1); epilogue packs fp16 into A cols [2048,6144)
    gemm_f16<true><<<dim3(N_HID / BN, BATCH / BM), 256, SMEM_GEMM>>>(
        (const __half*)pA, KA,
        (const __half*)pB1, N_IN,
        N_IN / BK,
        (__half*)pA, N_IN, nullptr, 0);

    // 4) GEMM2: out = [x | hidden] @ W2
    gemm_f16<false><<<dim3(N_OUT / BN, BATCH / BM), 256, SMEM_GEMM>>>(
        (const __half*)pA, KA,
        (const __half*)pB2, KA,
        KA / BK,
        nullptr, 0, out, N_OUT);
}